// round 15
// baseline (speedup 1.0000x reference)
#include <cuda_runtime.h>
#include <cuda_fp16.h>
#include <math.h>
#include <stdint.h>

// Problem constants
#define BATCH 4
#define TLEN  8192
#define EMB   1024
#define DH    64
#define MF    8
#define NJ    80          // 8 p_q + 8 p_k + 64 v
#define TM    128         // tokens per S-tile
#define MB    256         // tokens per CTA (2 tiles)
#define KC    32          // K per staged chunk
#define NCHUNK (EMB/KC)   // 32
#define NTILE ((BATCH*TLEN)/TM)   // 256
#define NBLK  (NTILE/2)   // 128
#define NFEAT (2*MF)
#define INV_SQRT_M 0.35355339059327376f

// ---- device scratch (no allocations allowed) ----
__device__ __half g_WBh[EMB*NJ];          // folded W [e][j] fp16 hi
__device__ __half g_WBl[EMB*NJ];          // fp16 lo residual (cols 0..15 used)
__device__ float g_bias[NJ];
__device__ float g_qP[BATCH*TLEN*NFEAT];  // finished q features (2 MB)
__device__ float g_Spart[NTILE*NFEAT*DH];
__device__ float g_S[BATCH*NFEAT*DH];

// ---- smem stage layout (per stage, M=256) ----
#define OFF_ALO 20480      // a_hi[256][40] half = 20480 B
#define OFF_BHI 40960      // a_lo same
#define OFF_BLO 46592      // b_hi[32][88] = 5632 B ; b_lo[32][24] = 1536 B
#define STAGE_BYTES 48128
#define DYN_BYTES (2 * STAGE_BYTES)   // 96256 -> 1 CTA/SM

// ---- epilogue panel layout (aliases stage smem; per 128-token tile) ----
#define P_KPH 0            // Kp hi [128][24] half, 48 B rows (6144 B)
#define P_KPL 6144
#define P_VH  12288        // V hi [128][72] half, 144 B rows (18432 B)
#define P_VL  30720        // ends 49152 < 96256

// ---- helpers ----
__device__ __forceinline__ uint32_t smem_u32(const void* p) {
    uint32_t a;
    asm("{ .reg .u64 t; cvta.to.shared.u64 t, %1; cvt.u32.u64 %0, t; }" : "=r"(a) : "l"(p));
    return a;
}
__device__ __forceinline__ void ldsm_x4(uint32_t* r, uint32_t addr) {
    asm volatile("ldmatrix.sync.aligned.m8n8.x4.shared.b16 {%0,%1,%2,%3}, [%4];"
        : "=r"(r[0]), "=r"(r[1]), "=r"(r[2]), "=r"(r[3]) : "r"(addr));
}
__device__ __forceinline__ void ldsm_x4_t(uint32_t* r, uint32_t addr) {
    asm volatile("ldmatrix.sync.aligned.m8n8.x4.trans.shared.b16 {%0,%1,%2,%3}, [%4];"
        : "=r"(r[0]), "=r"(r[1]), "=r"(r[2]), "=r"(r[3]) : "r"(addr));
}
__device__ __forceinline__ void mma_f16(float* c, const uint32_t* a, const uint32_t* b) {
    asm volatile("mma.sync.aligned.m16n8k16.row.col.f32.f16.f16.f32 "
        "{%0,%1,%2,%3}, {%4,%5,%6,%7}, {%8,%9}, {%0,%1,%2,%3};"
        : "+f"(c[0]), "+f"(c[1]), "+f"(c[2]), "+f"(c[3])
        : "r"(a[0]), "r"(a[1]), "r"(a[2]), "r"(a[3]), "r"(b[0]), "r"(b[1]));
}
__device__ __forceinline__ void split_pack(float vx, float vy, uint32_t& hi, uint32_t& lo) {
    __half2 h = __floats2half2_rn(vx, vy);
    float2 hf = __half22float2(h);
    __half2 l = __floats2half2_rn(vx - hf.x, vy - hf.y);
    hi = *reinterpret_cast<uint32_t*>(&h);
    lo = *reinterpret_cast<uint32_t*>(&l);
}

// ============================================================
// prep: fold Wq@w, Wk@w + Wv into fp16 hi/lo [e][j]; biases.
// ============================================================
__global__ void prep_kernel(const float* __restrict__ w,
                            const float* __restrict__ Wq, const float* __restrict__ bq,
                            const float* __restrict__ Wk, const float* __restrict__ bk,
                            const float* __restrict__ Wv, const float* __restrict__ bv) {
    int g = blockIdx.x * blockDim.x + threadIdx.x;
    if (g < NJ) {
        float bb;
        if (g < MF) {
            float s0 = 0.f, s1 = 0.f, s2 = 0.f, s3 = 0.f;
            for (int d = 0; d < DH; d += 4) {
                s0 += bq[d]     * w[(d)    *MF + g];
                s1 += bq[d + 1] * w[(d + 1)*MF + g];
                s2 += bq[d + 2] * w[(d + 2)*MF + g];
                s3 += bq[d + 3] * w[(d + 3)*MF + g];
            }
            bb = (s0 + s1) + (s2 + s3);
        } else if (g < 2*MF) {
            int jj = g - MF;
            float s0 = 0.f, s1 = 0.f, s2 = 0.f, s3 = 0.f;
            for (int d = 0; d < DH; d += 4) {
                s0 += bk[d]     * w[(d)    *MF + jj];
                s1 += bk[d + 1] * w[(d + 1)*MF + jj];
                s2 += bk[d + 2] * w[(d + 2)*MF + jj];
                s3 += bk[d + 3] * w[(d + 3)*MF + jj];
            }
            bb = (s0 + s1) + (s2 + s3);
        } else {
            bb = bv[g - 2*MF];
        }
        g_bias[g] = bb;
    }
    if (g >= EMB*NJ) return;
    int e = g / NJ;
    int j = g - e*NJ;
    float val;
    if (j < MF) {
        float s0 = 0.f, s1 = 0.f, s2 = 0.f, s3 = 0.f;
        for (int d = 0; d < DH; d += 4) {
            s0 += Wq[e*DH + d]     * w[(d)    *MF + j];
            s1 += Wq[e*DH + d + 1] * w[(d + 1)*MF + j];
            s2 += Wq[e*DH + d + 2] * w[(d + 2)*MF + j];
            s3 += Wq[e*DH + d + 3] * w[(d + 3)*MF + j];
        }
        val = (s0 + s1) + (s2 + s3);
    } else if (j < 2*MF) {
        int jj = j - MF;
        float s0 = 0.f, s1 = 0.f, s2 = 0.f, s3 = 0.f;
        for (int d = 0; d < DH; d += 4) {
            s0 += Wk[e*DH + d]     * w[(d)    *MF + jj];
            s1 += Wk[e*DH + d + 1] * w[(d + 1)*MF + jj];
            s2 += Wk[e*DH + d + 2] * w[(d + 2)*MF + jj];
            s3 += Wk[e*DH + d + 3] * w[(d + 3)*MF + jj];
        }
        val = (s0 + s1) + (s2 + s3);
    } else {
        val = Wv[e*DH + (j - 2*MF)];
    }
    __half h = __float2half_rn(val);
    g_WBh[g] = h;
    g_WBl[g] = __float2half_rn(val - __half2float(h));
}

// ============================================================
// phase 1: pipelined HMMA fp16 GEMM [256 x 80] per CTA.
// B fragments loaded once per chunk, applied to 2 M-tiles
// (halves redundant B ldsm smem traffic). MMA-based epilogue x2.
// ============================================================
__global__ __launch_bounds__(256, 1) void phase1_kernel(const float* __restrict__ x) {
    extern __shared__ char smc[];
    const int tid  = threadIdx.x;
    const int lane = tid & 31;
    const int w    = tid >> 5;                 // warp 0..7
    const int blk  = blockIdx.x;
    const float* xrow = x + (size_t)blk * MB * EMB;
    const uint32_t sbase = smem_u32(smc);

    // ldsm offsets within a stage (A: per tile t add t*128 rows)
    const uint32_t aOff0 = (uint32_t)((16*w + (lane & 15)) * 80 + ((lane >> 4) * 8) * 2);
    const uint32_t aOff1 = aOff0 + (uint32_t)(128 * 80);
    const uint32_t bOffHi = (uint32_t)(OFF_BHI + (lane & 15) * 176 + ((lane >> 4) * 8) * 2);
    const uint32_t bOffLo = (uint32_t)(OFF_BLO + (lane & 15) * 48  + ((lane >> 4) * 8) * 2);

    const int sa_tok = tid >> 3;               // + i*32, i<8 -> tok 0..255
    const int sa_k4  = (tid & 7) << 2;
    const int sl_k   = tid >> 3;
    const int sl_jp  = tid & 7;

    float acc[2][10][4];
    #pragma unroll
    for (int t = 0; t < 2; t++)
        #pragma unroll
        for (int nt = 0; nt < 10; nt++)
            #pragma unroll
            for (int i = 0; i < 4; i++) acc[t][nt][i] = 0.f;

    // ---- prologue: stage chunk 0 into stage 0 ----
    {
        char* sb = smc;
        #pragma unroll
        for (int i = 0; i < 8; i++) {
            int tok = sa_tok + i * 32;
            float4 v = *reinterpret_cast<const float4*>(xrow + (size_t)tok * EMB + sa_k4);
            uint32_t h0, l0, h1, l1;
            split_pack(v.x, v.y, h0, l0);
            split_pack(v.z, v.w, h1, l1);
            uint32_t off = (uint32_t)(tok * 80 + sa_k4 * 2);
            *reinterpret_cast<uint2*>(sb + off)           = make_uint2(h0, h1);
            *reinterpret_cast<uint2*>(sb + OFF_ALO + off) = make_uint2(l0, l1);
        }
        #pragma unroll
        for (int i = 0; i < 5; i++) {
            int idx = tid + i * 256;
            int k  = idx / 40;
            int jp = idx - k * 40;
            *reinterpret_cast<uint32_t*>(sb + OFF_BHI + k * 176 + jp * 4) =
                *reinterpret_cast<const uint32_t*>(&g_WBh[(size_t)k * NJ + 2 * jp]);
        }
        *reinterpret_cast<uint32_t*>(sb + OFF_BLO + sl_k * 48 + sl_jp * 4) =
            *reinterpret_cast<const uint32_t*>(&g_WBl[(size_t)sl_k * NJ + 2 * sl_jp]);
    }
    __syncthreads();

    // ---- pipelined main loop ----
    for (int c = 0; c < NCHUNK; c++) {
        const uint32_t sOff = (uint32_t)((c & 1) * STAGE_BYTES);
        const int nxt = c + 1;

        // 1) prefetch chunk c+1 into registers
        float4 va[8];
        uint32_t wh[5], wl0;
        if (nxt < NCHUNK) {
            const int ko = nxt * KC;
            #pragma unroll
            for (int i = 0; i < 8; i++) {
                int tok = sa_tok + i * 32;
                va[i] = *reinterpret_cast<const float4*>(xrow + (size_t)tok * EMB + ko + sa_k4);
            }
            #pragma unroll
            for (int i = 0; i < 5; i++) {
                int idx = tid + i * 256;
                int k  = idx / 40;
                int jp = idx - k * 40;
                wh[i] = *reinterpret_cast<const uint32_t*>(&g_WBh[(size_t)(ko + k) * NJ + 2 * jp]);
            }
            wl0 = *reinterpret_cast<const uint32_t*>(&g_WBl[(size_t)(ko + sl_k) * NJ + 2 * sl_jp]);
        }

        // 2) compute chunk c: B frags loaded once, reused for 2 A-tiles
        const uint32_t aHi0 = sbase + sOff + aOff0;
        const uint32_t aHi1 = sbase + sOff + aOff1;
        const uint32_t bHiAddr = sbase + sOff + bOffHi;
        const uint32_t bLoAddr = sbase + sOff + bOffLo;
        #pragma unroll
        for (int ks = 0; ks < 2; ks++) {
            uint32_t Ah0[4], Al0[4], Ah1[4], Al1[4];
            ldsm_x4(Ah0, aHi0 + ks * 32);
            ldsm_x4(Al0, aHi0 + OFF_ALO + ks * 32);
            ldsm_x4(Ah1, aHi1 + ks * 32);
            ldsm_x4(Al1, aHi1 + OFF_ALO + ks * 32);
            // p-columns: 3-term split, both tiles
            {
                uint32_t Bh[4], Bl[4];
                ldsm_x4_t(Bh, bHiAddr + ks * 2816);
                ldsm_x4_t(Bl, bLoAddr + ks * 768);
                mma_f16(acc[0][0], Ah0, Bh + 0);
                mma_f16(acc[0][1], Ah0, Bh + 2);
                mma_f16(acc[1][0], Ah1, Bh + 0);
                mma_f16(acc[1][1], Ah1, Bh + 2);
                mma_f16(acc[0][0], Ah0, Bl + 0);
                mma_f16(acc[0][1], Ah0, Bl + 2);
                mma_f16(acc[1][0], Ah1, Bl + 0);
                mma_f16(acc[1][1], Ah1, Bl + 2);
                mma_f16(acc[0][0], Al0, Bh + 0);
                mma_f16(acc[0][1], Al0, Bh + 2);
                mma_f16(acc[1][0], Al1, Bh + 0);
                mma_f16(acc[1][1], Al1, Bh + 2);
            }
            // v-columns: 1-term, both tiles
            #pragma unroll
            for (int np = 1; np < 5; np++) {
                uint32_t Bh[4];
                ldsm_x4_t(Bh, bHiAddr + ks * 2816 + np * 32);
                mma_f16(acc[0][2*np],     Ah0, Bh + 0);
                mma_f16(acc[0][2*np + 1], Ah0, Bh + 2);
                mma_f16(acc[1][2*np],     Ah1, Bh + 0);
                mma_f16(acc[1][2*np + 1], Ah1, Bh + 2);
            }
        }

        // 3) convert + store chunk c+1 into the other stage
        if (nxt < NCHUNK) {
            char* sb = smc + (nxt & 1) * STAGE_BYTES;
            #pragma unroll
            for (int i = 0; i < 8; i++) {
                int tok = sa_tok + i * 32;
                uint32_t h0, l0, h1, l1;
                split_pack(va[i].x, va[i].y, h0, l0);
                split_pack(va[i].z, va[i].w, h1, l1);
                uint32_t off = (uint32_t)(tok * 80 + sa_k4 * 2);
                *reinterpret_cast<uint2*>(sb + off)           = make_uint2(h0, h1);
                *reinterpret_cast<uint2*>(sb + OFF_ALO + off) = make_uint2(l0, l1);
            }
            #pragma unroll
            for (int i = 0; i < 5; i++) {
                int idx = tid + i * 256;
                int k  = idx / 40;
                int jp = idx - k * 40;
                *reinterpret_cast<uint32_t*>(sb + OFF_BHI + k * 176 + jp * 4) = wh[i];
            }
            *reinterpret_cast<uint32_t*>(sb + OFF_BLO + sl_k * 48 + sl_jp * 4) = wl0;
        }
        __syncthreads();
    }

    // ================= MMA-based epilogue, per tile =================
    const int r0 = 16 * w + (lane >> 2);
    const int cq = 2 * (lane & 3);

    #pragma unroll
    for (int t = 0; t < 2; t++) {
        const int t0 = blk * MB + t * TM;
        const int tileIdx = blk * 2 + t;
        float (*ac)[4] = acc[t];

        // q-path: ac[0] + bias -> sincos -> g_qP
        {
            float2 b2 = *reinterpret_cast<const float2*>(&g_bias[cq]);
            float sv0, cv0, sv1, cv1;
            sincosf(ac[0][0] + b2.x, &sv0, &cv0);
            sincosf(ac[0][1] + b2.y, &sv1, &cv1);
            float* qp = g_qP + (size_t)(t0 + r0) * NFEAT;
            *reinterpret_cast<float2*>(qp + cq)      = make_float2(cv0*INV_SQRT_M, cv1*INV_SQRT_M);
            *reinterpret_cast<float2*>(qp + MF + cq) = make_float2(sv0*INV_SQRT_M, sv1*INV_SQRT_M);
            sincosf(ac[0][2] + b2.x, &sv0, &cv0);
            sincosf(ac[0][3] + b2.y, &sv1, &cv1);
            qp = g_qP + (size_t)(t0 + r0 + 8) * NFEAT;
            *reinterpret_cast<float2*>(qp + cq)      = make_float2(cv0*INV_SQRT_M, cv1*INV_SQRT_M);
            *reinterpret_cast<float2*>(qp + MF + cq) = make_float2(sv0*INV_SQRT_M, sv1*INV_SQRT_M);
        }
        // k-path: ac[1] + bias -> sincos -> Kp hi/lo panels
        {
            float2 b2 = *reinterpret_cast<const float2*>(&g_bias[8 + cq]);
            #pragma unroll
            for (int half = 0; half < 2; half++) {
                int row = r0 + half * 8;
                float sv0, cv0, sv1, cv1;
                sincosf(ac[1][2*half + 0] + b2.x, &sv0, &cv0);
                sincosf(ac[1][2*half + 1] + b2.y, &sv1, &cv1);
                uint32_t hi, lo;
                split_pack(cv0*INV_SQRT_M, cv1*INV_SQRT_M, hi, lo);
                *reinterpret_cast<uint32_t*>(smc + P_KPH + row*48 + 2*cq) = hi;
                *reinterpret_cast<uint32_t*>(smc + P_KPL + row*48 + 2*cq) = lo;
                split_pack(sv0*INV_SQRT_M, sv1*INV_SQRT_M, hi, lo);
                *reinterpret_cast<uint32_t*>(smc + P_KPH + row*48 + 16 + 2*cq) = hi;
                *reinterpret_cast<uint32_t*>(smc + P_KPL + row*48 + 16 + 2*cq) = lo;
            }
        }
        // v: ac[2..9] + bias -> V hi/lo panels
        #pragma unroll
        for (int nt = 2; nt < 10; nt++) {
            int dcol = (nt - 2) * 8 + cq;
            float2 b2 = *reinterpret_cast<const float2*>(&g_bias[nt*8 + cq]);
            uint32_t hi, lo;
            split_pack(ac[nt][0] + b2.x, ac[nt][1] + b2.y, hi, lo);
            *reinterpret_cast<uint32_t*>(smc + P_VH + r0*144 + 2*dcol) = hi;
            *reinterpret_cast<uint32_t*>(smc + P_VL + r0*144 + 2*dcol) = lo;
            split_pack(ac[nt][2] + b2.x, ac[nt][3] + b2.y, hi, lo);
            *reinterpret_cast<uint32_t*>(smc + P_VH + (r0+8)*144 + 2*dcol) = hi;
            *reinterpret_cast<uint32_t*>(smc + P_VL + (r0+8)*144 + 2*dcol) = lo;
        }
        __syncwarp();

        // ldsm: A = Kp^T via trans-ldsm; B = V via trans-ldsm
        uint32_t Akh[4], Akl[4];
        {
            uint32_t aoff = (uint32_t)((16*w + (lane & 7) + ((lane & 16) >> 1)) * 48 + (lane & 8) * 2);
            ldsm_x4_t(Akh, sbase + P_KPH + aoff);
            ldsm_x4_t(Akl, sbase + P_KPL + aoff);
        }
        uint32_t Vh4[4][4], Vl4[4][4];
        {
            uint32_t boff = (uint32_t)((16*w + (lane & 15)) * 144 + ((lane >> 4) * 8) * 2);
            #pragma unroll
            for (int g2 = 0; g2 < 4; g2++) {
                ldsm_x4_t(Vh4[g2], sbase + P_VH + boff + g2 * 32);
                ldsm_x4_t(Vl4[g2], sbase + P_VL + boff + g2 * 32);
            }
        }
        // S-partial: 3-term split MMA (Kh*Vh + Kh*Vl + Kl*Vh)
        float cs[8][4];
        #pragma unroll
        for (int nt = 0; nt < 8; nt++)
            #pragma unroll
            for (int i = 0; i < 4; i++) cs[nt][i] = 0.f;
        #pragma unroll
        for (int nt = 0; nt < 8; nt++) {
            int g2 = nt >> 1, sel = (nt & 1) * 2;
            mma_f16(cs[nt], Akh, &Vh4[g2][sel]);
            mma_f16(cs[nt], Akh, &Vl4[g2][sel]);
            mma_f16(cs[nt], Akl, &Vh4[g2][sel]);
        }
        __syncthreads();   // panel reads done -> Sred may alias

        // per-warp partial S -> Sred[w][16][64], fixed-order combine
        float* Sred = reinterpret_cast<float*>(smc);
        {
            int f0 = lane >> 2;
            #pragma unroll
            for (int nt = 0; nt < 8; nt++) {
                int dd = nt * 8 + cq;
                *reinterpret_cast<float2*>(&Sred[w*1024 + f0*64 + dd])     = make_float2(cs[nt][0], cs[nt][1]);
                *reinterpret_cast<float2*>(&Sred[w*1024 + (f0+8)*64 + dd]) = make_float2(cs[nt][2], cs[nt][3]);
            }
        }
        __syncthreads();
        #pragma unroll
        for (int i = 0; i < 4; i++) {
            int slot = tid + i * 256;
            float s = 0.f;
            #pragma unroll
            for (int ww = 0; ww < 8; ww++) s += Sred[ww*1024 + slot];
            g_Spart[(size_t)tileIdx * (NFEAT*DH) + slot] = s;
        }
        __syncthreads();   // Sred consumed -> next tile may overwrite panels
    }
}

// ============================================================
// reduce: S[b][f][d] = sum over 64 tiles. 4 threads per (b,fd).
// ============================================================
__global__ __launch_bounds__(256) void reduce_kernel() {
    __shared__ float partial[4][64];
    const int tid = threadIdx.x;
    const int fdl  = tid & 63;
    const int part = tid >> 6;
    const int b      = blockIdx.x >> 4;
    const int fdbase = (blockIdx.x & 15) * 64;
    const int fd     = fdbase + fdl;

    const float* bs = g_Spart + (size_t)b * 64 * (NFEAT * DH) + fd;
    float s = 0.f;
    #pragma unroll
    for (int tt = 0; tt < 16; tt++)
        s += bs[(size_t)(part * 16 + tt) * (NFEAT * DH)];
    partial[part][fdl] = s;
    __syncthreads();
    if (part == 0) {
        float r = ((partial[0][fdl] + partial[1][fdl]) +
                   (partial[2][fdl] + partial[3][fdl]));
        g_S[b * (NFEAT * DH) + fd] = r;
    }
}

// ============================================================
// phase 2: y[t][d] = sum_f qP[t][f] * S[b][f][d]
// ============================================================
__global__ __launch_bounds__(128) void phase2_kernel(float* __restrict__ y) {
    __shared__ float Ss[NFEAT * DH];    // 4 KB
    __shared__ float qs[32][20];        // 2.5 KB
    const int tid  = threadIdx.x;
    const int lane = tid & 31;
    const int wp   = tid >> 5;
    const int t0   = blockIdx.x * 32;
    const int b    = t0 / TLEN;

    #pragma unroll
    for (int i = 0; i < 8; i++) Ss[tid + i * 128] = g_S[b * (NFEAT * DH) + tid + i * 128];
    {
        int idx = tid;                  // 128 float4s = 32 tokens x 16 feats
        float4 v = *reinterpret_cast<const float4*>(g_qP + (size_t)t0 * NFEAT + idx * 4);
        *reinterpret_cast<float4*>(&qs[idx >> 2][(idx & 3) * 4]) = v;
    }
    __syncthreads();

    float2 Sreg[NFEAT];
    #pragma unroll
    for (int f = 0; f < NFEAT; f++)
        Sreg[f] = *reinterpret_cast<const float2*>(&Ss[f * DH + 2 * lane]);

    #pragma unroll
    for (int it = 0; it < 8; it++) {
        int tok = wp * 8 + it;
        const float4* qv = reinterpret_cast<const float4*>(qs[tok]);
        float2 o = make_float2(0.f, 0.f);
        #pragma unroll
        for (int j = 0; j < 4; j++) {
            float4 q4 = qv[j];
            o.x = fmaf(q4.x, Sreg[4*j + 0].x, o.x); o.y = fmaf(q4.x, Sreg[4*j + 0].y, o.y);
            o.x = fmaf(q4.y, Sreg[4*j + 1].x, o.x); o.y = fmaf(q4.y, Sreg[4*j + 1].y, o.y);
            o.x = fmaf(q4.z, Sreg[4*j + 2].x, o.x); o.y = fmaf(q4.z, Sreg[4*j + 2].y, o.y);
            o.x = fmaf(q4.w, Sreg[4*j + 3].x, o.x); o.y = fmaf(q4.w, Sreg[4*j + 3].y, o.y);
        }
        *reinterpret_cast<float2*>(y + (size_t)(t0 + tok) * DH + 2 * lane) = o;
    }
}

// ============================================================
extern "C" void kernel_launch(void* const* d_in, const int* in_sizes, int n_in,
                              void* d_out, int out_size) {
    (void)in_sizes; (void)n_in; (void)out_size;
    const float* x  = (const float*)d_in[0];
    const float* w  = (const float*)d_in[1];
    const float* Wq = (const float*)d_in[2];
    const float* bq = (const float*)d_in[3];
    const float* Wk = (const float*)d_in[4];
    const float* bk = (const float*)d_in[5];
    const float* Wv = (const float*)d_in[6];
    const float* bv = (const float*)d_in[7];
    float* y = (float*)d_out;

    static int attr_set = 0;
    if (!attr_set) {
        cudaFuncSetAttribute(phase1_kernel, cudaFuncAttributeMaxDynamicSharedMemorySize, DYN_BYTES);
        attr_set = 1;
    }

    prep_kernel<<<(EMB * NJ + 255) / 256, 256>>>(w, Wq, bq, Wk, bk, Wv, bv);
    phase1_kernel<<<NBLK, 256, DYN_BYTES>>>(x);
    reduce_kernel<<<64, 256>>>();
    phase2_kernel<<<(BATCH * TLEN) / 32, 128>>>(y);
}